// round 6
// baseline (speedup 1.0000x reference)
#include <cuda_runtime.h>

// MPA_37056977830474 — M=4, F=4, V=6 fixed-shape message-passing step.
// Single warp, uniform task layout (best-measured variant, R3 structure):
//  - fa_n, FN_index, VN_index, w0, m, n loaded DIRECTLY into registers at
//    entry (static per-thread addresses, all L2 trips overlapped).
//  - Only IVF (dynamic-column gather) and IFV (cross-lane exchange) in SMEM.
//  - Exactly 2 __syncwarp on the critical path; 48 contraction tasks as
//    2 uniform reps over 32 lanes (no lane specialization — measured faster
//    than the divergent/specialized variants).
//
// Input order: [0]num_M [1]num_FN [2]num_VN [3]IVF(4x4x6 f32)
//              [4]VN_index(2x6 i32) [5]m(i32) [6]n(i32)
//              [7]FN_index(4x3 i32) [8]fa_n(4x4x4x4 f32) [9]w0(4x4x6 f32)
// Output: 4x4x6 f32.

#define M_ 4
#define F_ 4
#define V_ 6
#define FV (F_ * V_)   // 24

__global__ void __launch_bounds__(32, 1)
mpa_kernel(const float* __restrict__ IVF,
           const int*   __restrict__ VN_index,
           const int*   __restrict__ m_ptr,
           const int*   __restrict__ n_ptr,
           const int*   __restrict__ FN_index,
           const float* __restrict__ fa_n,
           const float* __restrict__ w0,
           float*       __restrict__ out) {
    __shared__ float s_IVF[M_ * FV];   // [a*24 + f*6 + v]
    __shared__ float s_IFV[M_ * FV];

    const int t = threadIdx.x;  // 0..31

    // ================= stage: issue every global load up front ===============
    if (t < 24) ((float4*)s_IVF)[t] = ((const float4*)IVF)[t];
    // zero IFV (scatter fills only 48 of 96)
    s_IFV[t] = 0.0f; s_IFV[t + 32] = 0.0f; s_IFV[t + 64] = 0.0f;

    const int mm = m_ptr[0];
    const int nn = n_ptr[0];

    // output-phase operands (static per-thread addresses)
    float rw[3]; int vva[3], vvb[3];
    #pragma unroll
    for (int j = 0; j < 3; j++) {
        int idx = t + j * 32;           // 0..95
        int v = idx % V_;
        rw[j]  = w0[idx];
        vva[j] = VN_index[v];
        vvb[j] = VN_index[V_ + v];
    }

    // contraction tasks: id = k*16 + a*4 + f, 48 tasks, <=2 per lane.
    //   k=0: A0[a,f] = sum_{b,c} g1[b,f] g2[c,f] fa[f][c][a][b] -> IFV[a,f,FN[f,0]]
    //   k=1: A1[a,f] = sum_{b,c} g0[b,f] g2[c,f] fa[f][c][b][a] -> IFV[a,f,FN[f,1]]
    //   k=2: A2[a,f] = sum_{b,c} g0[b,f] g1[c,f] fa[f][a][b][c] -> IFV[a,f,FN[f,2]]
    // All fa addresses are static per task: load into registers now.
    int   c1[2], c2[2], ck[2];
    float fv[2][16];
    int   aa[2], ff[2];
    bool  act[2];
    #pragma unroll
    for (int rep = 0; rep < 2; rep++) {
        int id = t + rep * 32;
        act[rep] = (id < 48);
        int k = (id >> 4) & 3, r = id & 15;
        aa[rep] = r >> 2; ff[rep] = r & 3;
        if (act[rep]) {
            int f = ff[rep], a = aa[rep];
            int k1 = (k == 0) ? 1 : 0;
            int k2 = (k == 2) ? 1 : 2;
            c1[rep] = FN_index[f * 3 + k1];
            c2[rep] = FN_index[f * 3 + k2];
            ck[rep] = FN_index[f * 3 + k];
            // fa[f][c][a][b] / fa[f][c][b][a] / fa[f][a][b][c] as base + b*cb + c*cc
            int cb   = (k == 0) ? 1 : 4;
            int cc   = (k == 2) ? 1 : 16;
            int base = f * 64 + ((k == 0) ? a * 4 : (k == 1) ? a : a * 16);
            #pragma unroll
            for (int b = 0; b < M_; b++)
                #pragma unroll
                for (int c = 0; c < M_; c++)
                    fv[rep][b * 4 + c] = __ldg(&fa_n[base + b * cb + c * cc]);
        }
    }

    __syncwarp();

    // ================= contraction + scatter =================================
    #pragma unroll
    for (int rep = 0; rep < 2; rep++) {
        if (act[rep]) {
            int f = ff[rep];
            float gx[M_], gy[M_];
            #pragma unroll
            for (int b = 0; b < M_; b++) {
                gx[b] = s_IVF[b * FV + f * V_ + c1[rep]];
                gy[b] = s_IVF[b * FV + f * V_ + c2[rep]];
            }
            float acc = 0.0f;
            #pragma unroll
            for (int b = 0; b < M_; b++)
                #pragma unroll
                for (int c = 0; c < M_; c++)
                    acc += gx[b] * gy[c] * fv[rep][b * 4 + c];
            // distinct columns per (a,f) row -> no collisions
            s_IFV[aa[rep] * FV + f * V_ + ck[rep]] = acc;
        }
    }

    __syncwarp();

    // ================= output (mean fused: IFV/sum == (IFV/M)/(sum/M)) =======
    const bool doUpdate = (mm < nn);
    #pragma unroll
    for (int j = 0; j < 3; j++) {
        int idx = t + j * 32;
        int a = idx / FV;
        int r = idx % FV;
        int f = r / V_;
        int v = r % V_;
        float val = s_IVF[idx];
        if (doUpdate) {
            int va = vva[j], vb = vvb[j];
            int src = (f == va) ? vb : (f == vb) ? va : -1;
            if (src >= 0) {
                int base = src * V_ + v;
                float sum = s_IFV[base] + s_IFV[base + FV] +
                            s_IFV[base + 2 * FV] + s_IFV[base + 3 * FV];
                val = __fdividef(s_IFV[a * FV + base], sum);
            }
            val *= rw[j];
        }
        out[idx] = val;
    }
}

extern "C" void kernel_launch(void* const* d_in, const int* in_sizes, int n_in,
                              void* d_out, int out_size) {
    const float* IVF      = (const float*)d_in[3];
    const int*   VN_index = (const int*)  d_in[4];
    const int*   m_ptr    = (const int*)  d_in[5];
    const int*   n_ptr    = (const int*)  d_in[6];
    const int*   FN_index = (const int*)  d_in[7];
    const float* fa_n     = (const float*)d_in[8];
    const float* w0       = (const float*)d_in[9];
    float* out = (float*)d_out;

    mpa_kernel<<<1, 32>>>(IVF, VN_index, m_ptr, n_ptr, FN_index, fa_n, w0, out);
}